// round 7
// baseline (speedup 1.0000x reference)
#include <cuda_runtime.h>
#include <cstdint>

#define N_NODES 100000
#define N_EDGES 6400000
#define ET      (N_EDGES / 4)   // edges per thread in scatter = 4
#define S_BKT   160             // bucket slots per node (mean deg 64, ~12 sigma headroom)

// ---- static device scratch ----
__device__ unsigned g_bucket[(size_t)N_NODES * S_BKT];  // 64 MB: row32 per (col, slot)
__device__ unsigned g_cnt [N_NODES];                    // in-degree (excl. self loop)
__device__ float    g_dinv[N_NODES];
__device__ float    g_xs  [N_NODES];                    // dinv[n] * x[n]
__device__ float2   g_zs  [N_NODES];                    // dinv[n] * z[n,0:2]
__device__ int      g_i64;

// K0: zero counters + dtype detection (device-side; graph-capturable)
__global__ void k_init(const unsigned* __restrict__ edge_words) {
    int n = blockIdx.x * blockDim.x + threadIdx.x;
    if (n < N_NODES) g_cnt[n] = 0u;
    if (blockIdx.x == 0 && threadIdx.x == 0) {
        // int64 layout: hi words all zero (indices in [0,100000)); int32: random.
        int i64 = 1;
        #pragma unroll
        for (int i = 0; i < 64; i++)
            if (edge_words[2 * i + 1] != 0u) i64 = 0;
        g_i64 = i64;
    }
}

// K1: single edge sweep — count degree AND build fixed-stride bucket CSR.
//     Replaces the old deg pass and the int64->int32 conversion, and removes
//     all atomics from the two aggregation passes.
__global__ void k_scatter(const void* __restrict__ edge) {
    int t = blockIdx.x * blockDim.x + threadIdx.x;
    if (t >= ET) return;
    unsigned r0, r1, r2, r3, c0, c1, c2, c3;
    if (g_i64) {
        const ulonglong2* rowp = (const ulonglong2*)edge;
        const ulonglong2* colp =
            (const ulonglong2*)((const unsigned long long*)edge + N_EDGES);
        ulonglong2 ra = __ldcs(&rowp[2 * t]);
        ulonglong2 rb = __ldcs(&rowp[2 * t + 1]);
        ulonglong2 ca = __ldcs(&colp[2 * t]);
        ulonglong2 cb = __ldcs(&colp[2 * t + 1]);
        r0 = (unsigned)ra.x; r1 = (unsigned)ra.y;
        r2 = (unsigned)rb.x; r3 = (unsigned)rb.y;
        c0 = (unsigned)ca.x; c1 = (unsigned)ca.y;
        c2 = (unsigned)cb.x; c3 = (unsigned)cb.y;
    } else {
        uint4 r = __ldcs(&((const uint4*)edge)[t]);
        const uint4* colp = (const uint4*)((const unsigned*)edge + N_EDGES);
        uint4 c = __ldcs(&colp[t]);
        r0 = r.x; r1 = r.y; r2 = r.z; r3 = r.w;
        c0 = c.x; c1 = c.y; c2 = c.z; c3 = c.w;
    }
    unsigned s;
    s = atomicAdd(&g_cnt[c0], 1u); if (s < S_BKT) g_bucket[(size_t)c0 * S_BKT + s] = r0;
    s = atomicAdd(&g_cnt[c1], 1u); if (s < S_BKT) g_bucket[(size_t)c1 * S_BKT + s] = r1;
    s = atomicAdd(&g_cnt[c2], 1u); if (s < S_BKT) g_bucket[(size_t)c2 * S_BKT + s] = r2;
    s = atomicAdd(&g_cnt[c3], 1u); if (s < S_BKT) g_bucket[(size_t)c3 * S_BKT + s] = r3;
}

// K2: dinv = (cnt+1)^-1/2 (self loop) ; xs = dinv * x
__global__ void k_node1(const float* __restrict__ x) {
    int n = blockIdx.x * blockDim.x + threadIdx.x;
    if (n >= N_NODES) return;
    float d = rsqrtf((float)(g_cnt[n] + 1u));
    g_dinv[n] = d;
    g_xs[n]   = d * x[n];
}

// K3: warp-per-node layer-1 aggregation (coalesced bucket read + random gather,
//     NO atomics) fused with per-node MLP -> zs.
__global__ void k_agg1(const float* __restrict__ W1, const float* __restrict__ b1,
                       const float* __restrict__ W2) {
    int w    = (blockIdx.x * blockDim.x + threadIdx.x) >> 5;
    int lane = threadIdx.x & 31;
    if (w >= N_NODES) return;
    unsigned deg = g_cnt[w];
    const unsigned* bp = g_bucket + (size_t)w * S_BKT;
    float sum = 0.f;
    for (unsigned s = lane; s < deg; s += 32)
        sum += g_xs[__ldcs(bp + s)];
    #pragma unroll
    for (int o = 16; o; o >>= 1)
        sum += __shfl_xor_sync(0xFFFFFFFFu, sum, o);
    if (lane == 0) {
        float d = g_dinv[w];
        float a = d * (sum + g_xs[w]);           // self-loop folded in
        float z0 = 0.f, z1 = 0.f;
        #pragma unroll
        for (int f = 0; f < 16; f++) {
            float h = fmaxf(fmaf(a, __ldg(W1 + f), __ldg(b1 + f)), 0.f);
            z0 = fmaf(__ldg(W2 + f),      h, z0);
            z1 = fmaf(__ldg(W2 + 16 + f), h, z1);
        }
        g_zs[w] = make_float2(d * z0, d * z1);
    }
}

// K4: warp-per-node layer-2 aggregation (float2 gather, NO atomics),
//     fused finalize: out = dinv*(sum + zs_self) + b2.  Coalesced output.
__global__ void k_agg2(float* __restrict__ out, const float* __restrict__ b2) {
    int w    = (blockIdx.x * blockDim.x + threadIdx.x) >> 5;
    int lane = threadIdx.x & 31;
    if (w >= N_NODES) return;
    unsigned deg = g_cnt[w];
    const unsigned* bp = g_bucket + (size_t)w * S_BKT;
    float s0 = 0.f, s1 = 0.f;
    for (unsigned s = lane; s < deg; s += 32) {
        float2 v = g_zs[__ldcs(bp + s)];
        s0 += v.x; s1 += v.y;
    }
    #pragma unroll
    for (int o = 16; o; o >>= 1) {
        s0 += __shfl_xor_sync(0xFFFFFFFFu, s0, o);
        s1 += __shfl_xor_sync(0xFFFFFFFFu, s1, o);
    }
    if (lane == 0) {
        float d  = g_dinv[w];
        float2 z = g_zs[w];
        ((float2*)out)[w] = make_float2(fmaf(d, s0 + z.x, __ldg(b2 + 0)),
                                        fmaf(d, s1 + z.y, __ldg(b2 + 1)));
    }
}

extern "C" void kernel_launch(void* const* d_in, const int* in_sizes, int n_in,
                              void* d_out, int out_size) {
    const float* x    = (const float*)d_in[0];
    const void*  edge = d_in[1];
    const float* W1   = (const float*)d_in[2];
    const float* b1   = (const float*)d_in[3];
    const float* W2   = (const float*)d_in[4];
    const float* b2   = (const float*)d_in[5];
    float* out = (float*)d_out;

    const int NT = 256;
    const int nodeBlocks = (N_NODES + NT - 1) / NT;          // 391
    const int edgeBlocks = (ET + NT - 1) / NT;               // 6250
    const int warpBlocks = (N_NODES * 32 + NT - 1) / NT;     // 12500 (warp per node)

    k_init   <<<nodeBlocks, NT>>>((const unsigned*)edge);
    k_scatter<<<edgeBlocks, NT>>>(edge);
    k_node1  <<<nodeBlocks, NT>>>(x);
    k_agg1   <<<warpBlocks, NT>>>(W1, b1, W2);
    k_agg2   <<<warpBlocks, NT>>>(out, b2);
}

// round 8
// speedup vs baseline: 1.0343x; 1.0343x over previous
#include <cuda_runtime.h>
#include <cstdint>

#define N_NODES 100000
#define N_EDGES 6400000
#define ET      (N_EDGES / 4)   // edges per thread = 4

// ---- static device scratch ----
__device__ uint2    g_pack[N_EDGES];    // 51.2 MB: packed (row,col) int32 pairs
__device__ unsigned g_cnt [N_NODES];    // in-degree (excl. self loop)
__device__ float    g_dinv[N_NODES];
__device__ float    g_xs  [N_NODES];    // dinv[n] * x[n]
__device__ float    g_agg1[N_NODES];
__device__ float2   g_zs  [N_NODES];    // dinv[n] * z[n,0:2]
__device__ int      g_i64;

__device__ __forceinline__ void red_add_f32(float* p, float v) {
    asm volatile("red.global.add.f32 [%0], %1;" :: "l"(p), "f"(v) : "memory");
}
__device__ __forceinline__ void red_add_u32(unsigned* p, unsigned v) {
    asm volatile("red.global.add.u32 [%0], %1;" :: "l"(p), "r"(v) : "memory");
}
__device__ __forceinline__ void red_add_v2f32(float* p, float a, float b) {
    asm volatile("red.global.add.v2.f32 [%0], {%1, %2};" :: "l"(p), "f"(a), "f"(b) : "memory");
}

// K0: zero counters/accumulators + dtype detection (device-side)
__global__ void k_init(const unsigned* __restrict__ edge_words) {
    int n = blockIdx.x * blockDim.x + threadIdx.x;
    if (n < N_NODES) { g_cnt[n] = 0u; g_agg1[n] = 0.f; }
    if (blockIdx.x == 0 && threadIdx.x == 0) {
        // int64 layout: hi words all zero (indices in [0,100000)); int32: random.
        int i64 = 1;
        #pragma unroll
        for (int i = 0; i < 64; i++)
            if (edge_words[2 * i + 1] != 0u) i64 = 0;
        g_i64 = i64;
    }
}

// K1: degree histogram over col + pack (row,col) into one int32-pair stream.
//     Hot passes A/B then read a single coalesced 8B/edge stream, no dtype branch.
__global__ void k_deg(const void* __restrict__ edge) {
    int t = blockIdx.x * blockDim.x + threadIdx.x;
    if (t >= ET) return;
    unsigned r0, r1, r2, r3, c0, c1, c2, c3;
    if (g_i64) {
        const ulonglong2* rowp = (const ulonglong2*)edge;
        const ulonglong2* colp =
            (const ulonglong2*)((const unsigned long long*)edge + N_EDGES);
        ulonglong2 ra = __ldcs(&rowp[2 * t]);
        ulonglong2 rb = __ldcs(&rowp[2 * t + 1]);
        ulonglong2 ca = __ldcs(&colp[2 * t]);
        ulonglong2 cb = __ldcs(&colp[2 * t + 1]);
        r0 = (unsigned)ra.x; r1 = (unsigned)ra.y;
        r2 = (unsigned)rb.x; r3 = (unsigned)rb.y;
        c0 = (unsigned)ca.x; c1 = (unsigned)ca.y;
        c2 = (unsigned)cb.x; c3 = (unsigned)cb.y;
    } else {
        uint4 r = __ldcs(&((const uint4*)edge)[t]);
        const uint4* colp = (const uint4*)((const unsigned*)edge + N_EDGES);
        uint4 c = __ldcs(&colp[t]);
        r0 = r.x; r1 = r.y; r2 = r.z; r3 = r.w;
        c0 = c.x; c1 = c.y; c2 = c.z; c3 = c.w;
    }
    uint4* pk = (uint4*)g_pack;                 // 2 edges per uint4
    __stcs(&pk[2 * t],     make_uint4(r0, c0, r1, c1));
    __stcs(&pk[2 * t + 1], make_uint4(r2, c2, r3, c3));
    red_add_u32(&g_cnt[c0], 1u);
    red_add_u32(&g_cnt[c1], 1u);
    red_add_u32(&g_cnt[c2], 1u);
    red_add_u32(&g_cnt[c3], 1u);
}

// K2: dinv = (deg+1)^-1/2 ; xs = dinv * x
__global__ void k_node1(const float* __restrict__ x) {
    int n = blockIdx.x * blockDim.x + threadIdx.x;
    if (n >= N_NODES) return;
    float d = rsqrtf((float)(g_cnt[n] + 1u));   // +1 = self loop
    g_dinv[n] = d;
    g_xs[n]   = d * x[n];
}

// K3: edge pass A — agg1[col] += xs[row].  1 coalesced 8B stream + 1 L1-cached
//     gather + 1 red per edge.
__global__ void k_edgeA() {
    int t = blockIdx.x * blockDim.x + threadIdx.x;
    if (t >= ET) return;
    const uint4* pk = (const uint4*)g_pack;
    uint4 a = __ldcs(&pk[2 * t]);       // r0,c0,r1,c1
    uint4 b = __ldcs(&pk[2 * t + 1]);   // r2,c2,r3,c3
    float v0 = __ldg(&g_xs[a.x]);
    float v1 = __ldg(&g_xs[a.z]);
    float v2 = __ldg(&g_xs[b.x]);
    float v3 = __ldg(&g_xs[b.z]);
    red_add_f32(&g_agg1[a.y], v0);
    red_add_f32(&g_agg1[a.w], v1);
    red_add_f32(&g_agg1[b.y], v2);
    red_add_f32(&g_agg1[b.w], v3);
}

// K4: per-node MLP: a = dinv*(agg1 + xs_self); h=relu(a*W1+b1); z=W2 h;
//     zs = dinv*z; zero the d_out accumulators.
__global__ void k_node2(const float* __restrict__ W1, const float* __restrict__ b1,
                        const float* __restrict__ W2, float* __restrict__ out) {
    int n = blockIdx.x * blockDim.x + threadIdx.x;
    if (n >= N_NODES) return;
    float d = g_dinv[n];
    float a = d * (g_agg1[n] + g_xs[n]);
    float z0 = 0.f, z1 = 0.f;
    #pragma unroll
    for (int f = 0; f < 16; f++) {
        float h = fmaxf(fmaf(a, __ldg(W1 + f), __ldg(b1 + f)), 0.f);
        z0 = fmaf(__ldg(W2 + f),      h, z0);
        z1 = fmaf(__ldg(W2 + 16 + f), h, z1);
    }
    g_zs[n] = make_float2(d * z0, d * z1);
    ((float2*)out)[n] = make_float2(0.f, 0.f);
}

// K5: edge pass B — out[col,0:2] += zs[row]  (vector red)
__global__ void k_edgeB(float* __restrict__ out) {
    int t = blockIdx.x * blockDim.x + threadIdx.x;
    if (t >= ET) return;
    const uint4* pk = (const uint4*)g_pack;
    uint4 a = __ldcs(&pk[2 * t]);
    uint4 b = __ldcs(&pk[2 * t + 1]);
    float2 v0 = __ldg(&g_zs[a.x]);
    float2 v1 = __ldg(&g_zs[a.z]);
    float2 v2 = __ldg(&g_zs[b.x]);
    float2 v3 = __ldg(&g_zs[b.z]);
    red_add_v2f32(out + 2 * (size_t)a.y, v0.x, v0.y);
    red_add_v2f32(out + 2 * (size_t)a.w, v1.x, v1.y);
    red_add_v2f32(out + 2 * (size_t)b.y, v2.x, v2.y);
    red_add_v2f32(out + 2 * (size_t)b.w, v3.x, v3.y);
}

// K6: finalize: out = dinv*(acc + zs_self) + b2
__global__ void k_node3(float* __restrict__ out, const float* __restrict__ b2) {
    int n = blockIdx.x * blockDim.x + threadIdx.x;
    if (n >= N_NODES) return;
    float d = g_dinv[n];
    float2 acc = ((float2*)out)[n];
    float2 zs  = g_zs[n];
    ((float2*)out)[n] = make_float2(fmaf(d, acc.x + zs.x, __ldg(b2 + 0)),
                                    fmaf(d, acc.y + zs.y, __ldg(b2 + 1)));
}

extern "C" void kernel_launch(void* const* d_in, const int* in_sizes, int n_in,
                              void* d_out, int out_size) {
    const float* x    = (const float*)d_in[0];
    const void*  edge = d_in[1];
    const float* W1   = (const float*)d_in[2];
    const float* b1   = (const float*)d_in[3];
    const float* W2   = (const float*)d_in[4];
    const float* b2   = (const float*)d_in[5];
    float* out = (float*)d_out;

    const int NT = 256;
    const int nodeBlocks = (N_NODES + NT - 1) / NT;   // 391
    const int edgeBlocks = (ET + NT - 1) / NT;        // 6250

    k_init <<<nodeBlocks, NT>>>((const unsigned*)edge);
    k_deg  <<<edgeBlocks, NT>>>(edge);
    k_node1<<<nodeBlocks, NT>>>(x);
    k_edgeA<<<edgeBlocks, NT>>>();
    k_node2<<<nodeBlocks, NT>>>(W1, b1, W2, out);
    k_edgeB<<<edgeBlocks, NT>>>(out);
    k_node3<<<nodeBlocks, NT>>>(out, b2);
}

// round 9
// speedup vs baseline: 1.0631x; 1.0279x over previous
#include <cuda_runtime.h>
#include <cstdint>

#define N_NODES  100000
#define N_EDGES  6400000
#define NT       256
#define EPT      4                     // edges per thread in k_deg
#define EPB      (NT * EPT)            // 1024 edges per block
#define NPARTS   4
#define NPP      25000                 // nodes per partition (row range)
#define PART_CAP 1665024               // slots per partition (mean 1.6M, ~60σ margin)

// ---- static device scratch ----
__device__ uint2    g_pack[(size_t)NPARTS * PART_CAP];  // ~53 MB: (row,col) per partition
__device__ unsigned g_pcnt[NPARTS];                     // edges per partition
__device__ unsigned g_cnt [N_NODES];                    // in-degree (excl. self loop)
__device__ float    g_dinv[N_NODES];
__device__ float    g_xs  [N_NODES];                    // dinv[n] * x[n]
__device__ float    g_agg1[N_NODES];
__device__ float2   g_zs  [N_NODES];                    // dinv[n] * z[n,0:2]
__device__ int      g_i64;

__device__ __forceinline__ void red_add_f32(float* p, float v) {
    asm volatile("red.global.add.f32 [%0], %1;" :: "l"(p), "f"(v) : "memory");
}
__device__ __forceinline__ void red_add_u32(unsigned* p, unsigned v) {
    asm volatile("red.global.add.u32 [%0], %1;" :: "l"(p), "r"(v) : "memory");
}
__device__ __forceinline__ void red_add_v2f32(float* p, float a, float b) {
    asm volatile("red.global.add.v2.f32 [%0], {%1, %2};" :: "l"(p), "f"(a), "f"(b) : "memory");
}

// K0: zero counters + dtype detection (device-side; graph-capturable)
__global__ void k_init(const unsigned* __restrict__ edge_words) {
    int n = blockIdx.x * blockDim.x + threadIdx.x;
    if (n < N_NODES) { g_cnt[n] = 0u; g_agg1[n] = 0.f; }
    if (n < NPARTS)  g_pcnt[n] = 0u;
    if (blockIdx.x == 0 && threadIdx.x == 0) {
        // int64 layout: hi words all zero (indices in [0,100000)); int32: random.
        int i64 = 1;
        #pragma unroll
        for (int i = 0; i < 64; i++)
            if (edge_words[2 * i + 1] != 0u) i64 = 0;
        g_i64 = i64;
    }
}

// K1: degree histogram over col + partition (row,col) pairs by row/25000.
//     Block stages its 1024 edges in SMEM grouped by partition, reserves global
//     ranges with 4 atomics, then copies out coalesced.
__global__ void k_deg(const void* __restrict__ edge) {
    __shared__ unsigned scnt[NPARTS];
    __shared__ unsigned sbase[NPARTS];
    __shared__ unsigned sseg[NPARTS + 1];
    __shared__ uint2    sbuf[EPB];

    int tid = threadIdx.x;
    int t   = blockIdx.x * NT + tid;
    if (tid < NPARTS) scnt[tid] = 0u;
    __syncthreads();

    unsigned r[EPT], c[EPT];
    if (g_i64) {
        const ulonglong2* rowp = (const ulonglong2*)edge;
        const ulonglong2* colp =
            (const ulonglong2*)((const unsigned long long*)edge + N_EDGES);
        ulonglong2 ra = __ldcs(&rowp[2 * t]);
        ulonglong2 rb = __ldcs(&rowp[2 * t + 1]);
        ulonglong2 ca = __ldcs(&colp[2 * t]);
        ulonglong2 cb = __ldcs(&colp[2 * t + 1]);
        r[0] = (unsigned)ra.x; r[1] = (unsigned)ra.y;
        r[2] = (unsigned)rb.x; r[3] = (unsigned)rb.y;
        c[0] = (unsigned)ca.x; c[1] = (unsigned)ca.y;
        c[2] = (unsigned)cb.x; c[3] = (unsigned)cb.y;
    } else {
        uint4 rr = __ldcs(&((const uint4*)edge)[t]);
        const uint4* colp = (const uint4*)((const unsigned*)edge + N_EDGES);
        uint4 cc = __ldcs(&colp[t]);
        r[0] = rr.x; r[1] = rr.y; r[2] = rr.z; r[3] = rr.w;
        c[0] = cc.x; c[1] = cc.y; c[2] = cc.z; c[3] = cc.w;
    }

    unsigned p[EPT], slot[EPT];
    #pragma unroll
    for (int i = 0; i < EPT; i++) {
        p[i]    = r[i] / NPP;
        slot[i] = atomicAdd(&scnt[p[i]], 1u);
        red_add_u32(&g_cnt[c[i]], 1u);          // degree (L2 red, no return)
    }
    __syncthreads();

    if (tid == 0) {
        unsigned acc = 0;
        #pragma unroll
        for (int q = 0; q < NPARTS; q++) {
            sseg[q] = acc;
            acc += scnt[q];
            sbase[q] = atomicAdd(&g_pcnt[q], scnt[q]);
        }
        sseg[NPARTS] = acc;
    }
    __syncthreads();

    #pragma unroll
    for (int i = 0; i < EPT; i++)
        sbuf[sseg[p[i]] + slot[i]] = make_uint2(r[i], c[i]);
    __syncthreads();

    // coalesced copy-out: smem is partition-ordered; each segment maps to a
    // contiguous chunk of its partition's global region.
    for (int j = tid; j < EPB; j += NT) {
        unsigned q = 0;
        #pragma unroll
        for (int k = 1; k < NPARTS; k++) if (j >= sseg[k]) q = k;
        unsigned pos = sbase[q] + (unsigned)(j - sseg[q]);
        if (pos < PART_CAP)
            __stcs(&g_pack[(size_t)q * PART_CAP + pos], sbuf[j]);
    }
}

// K2: dinv = (deg+1)^-1/2 ; xs = dinv * x
__global__ void k_node1(const float* __restrict__ x) {
    int n = blockIdx.x * blockDim.x + threadIdx.x;
    if (n >= N_NODES) return;
    float d = rsqrtf((float)(g_cnt[n] + 1u));
    g_dinv[n] = d;
    g_xs[n]   = d * x[n];
}

// K3: edge pass A over ONE partition — gather window is 100KB of g_xs,
//     fully L1-resident.  agg1[col] += xs[row].
__global__ void k_edgeA(int part) {
    unsigned cnt = g_pcnt[part];
    unsigned i   = blockIdx.x * blockDim.x + threadIdx.x;
    if (i >= cnt) return;
    uint2 e = __ldcs(&g_pack[(size_t)part * PART_CAP + i]);
    float v = __ldg(&g_xs[e.x]);
    red_add_f32(&g_agg1[e.y], v);
}

// K4: per-node MLP -> zs; zero the d_out accumulators.
__global__ void k_node2(const float* __restrict__ W1, const float* __restrict__ b1,
                        const float* __restrict__ W2, float* __restrict__ out) {
    int n = blockIdx.x * blockDim.x + threadIdx.x;
    if (n >= N_NODES) return;
    float d = g_dinv[n];
    float a = d * (g_agg1[n] + g_xs[n]);        // self-loop folded in
    float z0 = 0.f, z1 = 0.f;
    #pragma unroll
    for (int f = 0; f < 16; f++) {
        float h = fmaxf(fmaf(a, __ldg(W1 + f), __ldg(b1 + f)), 0.f);
        z0 = fmaf(__ldg(W2 + f),      h, z0);
        z1 = fmaf(__ldg(W2 + 16 + f), h, z1);
    }
    g_zs[n] = make_float2(d * z0, d * z1);
    ((float2*)out)[n] = make_float2(0.f, 0.f);
}

// K5: edge pass B over ONE partition — gather window is 200KB of g_zs
//     (fits 228KB L1).  out[col,0:2] += zs[row].
__global__ void k_edgeB(int part, float* __restrict__ out) {
    unsigned cnt = g_pcnt[part];
    unsigned i   = blockIdx.x * blockDim.x + threadIdx.x;
    if (i >= cnt) return;
    uint2 e = __ldcs(&g_pack[(size_t)part * PART_CAP + i]);
    float2 v = __ldg(&g_zs[e.x]);
    red_add_v2f32(out + 2 * (size_t)e.y, v.x, v.y);
}

// K6: finalize: out = dinv*(acc + zs_self) + b2
__global__ void k_node3(float* __restrict__ out, const float* __restrict__ b2) {
    int n = blockIdx.x * blockDim.x + threadIdx.x;
    if (n >= N_NODES) return;
    float d = g_dinv[n];
    float2 acc = ((float2*)out)[n];
    float2 zs  = g_zs[n];
    ((float2*)out)[n] = make_float2(fmaf(d, acc.x + zs.x, __ldg(b2 + 0)),
                                    fmaf(d, acc.y + zs.y, __ldg(b2 + 1)));
}

extern "C" void kernel_launch(void* const* d_in, const int* in_sizes, int n_in,
                              void* d_out, int out_size) {
    const float* x    = (const float*)d_in[0];
    const void*  edge = d_in[1];
    const float* W1   = (const float*)d_in[2];
    const float* b1   = (const float*)d_in[3];
    const float* W2   = (const float*)d_in[4];
    const float* b2   = (const float*)d_in[5];
    float* out = (float*)d_out;

    const int nodeBlocks = (N_NODES + NT - 1) / NT;      // 391
    const int degBlocks  = N_EDGES / EPB;                // 6250
    const int partBlocks = (PART_CAP + NT - 1) / NT;     // 6504

    k_init <<<nodeBlocks, NT>>>((const unsigned*)edge);
    k_deg  <<<degBlocks, NT>>>(edge);
    k_node1<<<nodeBlocks, NT>>>(x);
    for (int p = 0; p < NPARTS; p++)
        k_edgeA<<<partBlocks, NT>>>(p);
    k_node2<<<nodeBlocks, NT>>>(W1, b1, W2, out);
    for (int p = 0; p < NPARTS; p++)
        k_edgeB<<<partBlocks, NT>>>(p, out);
    k_node3<<<nodeBlocks, NT>>>(out, b2);
}